// round 1
// baseline (speedup 1.0000x reference)
#include <cuda_runtime.h>
#include <math.h>

#define BATCH   2
#define LSEQ    1024
#define DM      1024
#define DI      2048
#define DSTATE  16
#define DTRANK  64
#define NROWS   (BATCH*LSEQ)   // 2048
#define XPN     96             // DT_RANK + 2*D_STATE

// -------- scratch (device globals; no allocation allowed) --------
__device__ float g_hnorm[NROWS*DM];
__device__ float g_xz[NROWS*2*DI];
__device__ float g_xc[NROWS*DI];
__device__ float g_xdbl[NROWS*XPN];
__device__ float g_dt[NROWS*DI];
__device__ float g_y[NROWS*DI];

// -------- f32x2 helpers (FFMA2 path: 2x fp32 FMA throughput on sm_103a) ---
__device__ __forceinline__ unsigned long long pack2(float x, float y){
  unsigned long long r; asm("mov.b64 %0, {%1,%2};" : "=l"(r) : "f"(x), "f"(y)); return r;
}
__device__ __forceinline__ float2 unpack2(unsigned long long v){
  float2 r; asm("mov.b64 {%0,%1}, %2;" : "=f"(r.x), "=f"(r.y) : "l"(v)); return r;
}
__device__ __forceinline__ void fma2(unsigned long long& c, unsigned long long a, unsigned long long b){
  asm("fma.rn.f32x2 %0, %1, %2, %0;" : "+l"(c) : "l"(a), "l"(b));
}
__device__ __forceinline__ float softplus_f(float x){
  return (x > 20.f) ? x : log1pf(expf(x));
}

// ---------------- RMSNorm (faithful: rms = ||x||/sqrt(d); x/(rms+eps)*w) ---
__global__ void rmsnorm_kernel(const float* __restrict__ x,
                               const float* __restrict__ w){
  int row = blockIdx.x;
  const float* xr = x + (size_t)row*DM;
  float ss = 0.f;
  for (int j = threadIdx.x; j < DM; j += 256){ float v = xr[j]; ss += v*v; }
  __shared__ float red[8];
  for (int o = 16; o; o >>= 1) ss += __shfl_xor_sync(~0u, ss, o);
  if ((threadIdx.x & 31) == 0) red[threadIdx.x >> 5] = ss;
  __syncthreads();
  if (threadIdx.x < 8){
    float v = red[threadIdx.x];
    for (int o = 4; o; o >>= 1) v += __shfl_xor_sync(0xff, v, o, 8);
    if (threadIdx.x == 0) red[0] = v;
  }
  __syncthreads();
  float rms = sqrtf(red[0]) * (1.0f/32.0f);   // /sqrt(1024)
  float inv = 1.0f/(rms + 1e-5f);
  for (int j = threadIdx.x; j < DM; j += 256)
    g_hnorm[(size_t)row*DM + j] = xr[j]*inv*w[j];
}

// ---------------- Tiled TN SGEMM with f32x2 inner product -----------------
// C[m,n] = sum_k A[m*lda+k] * B[n*ldb+k]
// EPI: 0 = store, 1 = softplus(acc + bias[n]) store, 2 = atomicAdd (split-K)
#define BM 128
#define BN 128
#define BK 16
#define TPAD 132

template<int EPI>
__global__ __launch_bounds__(256,2) void sgemm_tn(
    const float* __restrict__ A, int lda,
    const float* __restrict__ B, int ldb,
    float* __restrict__ C, int ldc,
    int N, int kc, const float* __restrict__ bias)
{
  __shared__ __align__(16) float As[2][BK][TPAD];
  __shared__ __align__(16) float Bs[2][BK][TPAD];
  const int tid = threadIdx.x;
  const int bm = blockIdx.y * BM;
  const int bn = blockIdx.x * BN;
  const int kbase = blockIdx.z * kc;
  const int tx = tid & 15, ty = tid >> 4;
  const int r0 = tid >> 2;          // 0..63
  const int kq = (tid & 3) * 4;     // 0,4,8,12

  unsigned long long acc[8][4];
  #pragma unroll
  for (int i = 0; i < 8; i++)
    #pragma unroll
    for (int j = 0; j < 4; j++) acc[i][j] = 0ull;

  const float4 fzero4 = make_float4(0.f,0.f,0.f,0.f);
  float4 ra0, ra1, rb0, rb1;
  const int nt = kc / BK;

#define LOAD_TILE(tt) do {                                                   \
    int koff = kbase + (tt)*BK + kq;                                         \
    ra0 = *(const float4*)(A + (size_t)(bm+r0)*lda + koff);                  \
    ra1 = *(const float4*)(A + (size_t)(bm+r0+64)*lda + koff);               \
    int n0 = bn + r0, n1 = bn + r0 + 64;                                     \
    rb0 = (n0 < N) ? *(const float4*)(B + (size_t)n0*ldb + koff) : fzero4;   \
    rb1 = (n1 < N) ? *(const float4*)(B + (size_t)n1*ldb + koff) : fzero4;   \
  } while(0)

#define STORE_TILE(pp) do {                                                  \
    As[pp][kq+0][r0]=ra0.x; As[pp][kq+1][r0]=ra0.y;                          \
    As[pp][kq+2][r0]=ra0.z; As[pp][kq+3][r0]=ra0.w;                          \
    As[pp][kq+0][r0+64]=ra1.x; As[pp][kq+1][r0+64]=ra1.y;                    \
    As[pp][kq+2][r0+64]=ra1.z; As[pp][kq+3][r0+64]=ra1.w;                    \
    Bs[pp][kq+0][r0]=rb0.x; Bs[pp][kq+1][r0]=rb0.y;                          \
    Bs[pp][kq+2][r0]=rb0.z; Bs[pp][kq+3][r0]=rb0.w;                          \
    Bs[pp][kq+0][r0+64]=rb1.x; Bs[pp][kq+1][r0+64]=rb1.y;                    \
    Bs[pp][kq+2][r0+64]=rb1.z; Bs[pp][kq+3][r0+64]=rb1.w;                    \
  } while(0)

  LOAD_TILE(0);
  STORE_TILE(0);
  __syncthreads();

  int p = 0;
  for (int t = 0; t < nt; t++){
    const bool has_next = (t + 1 < nt);
    if (has_next) LOAD_TILE(t+1);

    #pragma unroll
    for (int kk = 0; kk < BK; kk++){
      float4 a0 = *(const float4*)&As[p][kk][ty*8];
      float4 a1 = *(const float4*)&As[p][kk][ty*8+4];
      const unsigned long long* bp =
          (const unsigned long long*)&Bs[p][kk][tx*8];
      unsigned long long b0 = bp[0], b1 = bp[1], b2 = bp[2], b3 = bp[3];
      float av[8] = {a0.x,a0.y,a0.z,a0.w,a1.x,a1.y,a1.z,a1.w};
      #pragma unroll
      for (int i = 0; i < 8; i++){
        unsigned long long ap = pack2(av[i], av[i]);
        fma2(acc[i][0], ap, b0);
        fma2(acc[i][1], ap, b1);
        fma2(acc[i][2], ap, b2);
        fma2(acc[i][3], ap, b3);
      }
    }
    if (has_next) STORE_TILE(p ^ 1);
    __syncthreads();
    p ^= 1;
  }

  // epilogue
  #pragma unroll
  for (int i = 0; i < 8; i++){
    int m = bm + ty*8 + i;
    float* Crow = C + (size_t)m*ldc;
    #pragma unroll
    for (int j = 0; j < 4; j++){
      int n = bn + tx*8 + 2*j;
      float2 v = unpack2(acc[i][j]);
      if (EPI == 0){
        if (n   < N) Crow[n]   = v.x;
        if (n+1 < N) Crow[n+1] = v.y;
      } else if (EPI == 1){
        if (n   < N) Crow[n]   = softplus_f(v.x + bias[n]);
        if (n+1 < N) Crow[n+1] = softplus_f(v.y + bias[n+1]);
      } else {
        if (n   < N) atomicAdd(&Crow[n],   v.x);
        if (n+1 < N) atomicAdd(&Crow[n+1], v.y);
      }
    }
  }
#undef LOAD_TILE
#undef STORE_TILE
}

// ---------------- causal depthwise conv (k=4) + SiLU ----------------------
__global__ void conv_silu_kernel(const float* __restrict__ conv_w,
                                 const float* __restrict__ conv_b){
  int idx = blockIdx.x*256 + threadIdx.x;          // over NROWS*DI
  int d   = idx & (DI-1);
  int row = idx >> 11;
  int l   = row & (LSEQ-1);
  int b   = row >> 10;
  float s = conv_b[d];
  const float* xcol = g_xz + ((size_t)b*LSEQ)*(2*DI) + d;   // x part
  #pragma unroll
  for (int k = 0; k < 4; k++){
    int ls = l - 3 + k;
    if (ls >= 0) s = fmaf(xcol[(size_t)ls*(2*DI)], conv_w[d*4+k], s);
  }
  s = s / (1.f + __expf(-s));                      // SiLU
  g_xc[idx] = s;
}

// ---------------- selective scan: 16 lanes per (b,d), shuffle reduce ------
__global__ void scan_kernel(const float* __restrict__ A_log,
                            const float* __restrict__ Dp){
  int gt = blockIdx.x*blockDim.x + threadIdx.x;    // 65536 threads
  int n  = gt & 15;
  int g  = gt >> 4;                                // (b,d) group
  int d  = g & (DI-1);
  int b  = g >> 11;
  float a  = -expf(A_log[d*DSTATE + n]);
  float Dd = Dp[d];
  float h  = 0.f;
  const float* dt_p = g_dt   + (size_t)b*LSEQ*DI + d;
  const float* xc_p = g_xc   + (size_t)b*LSEQ*DI + d;
  const float* bc_p = g_xdbl + (size_t)b*LSEQ*XPN + DTRANK;
  const float* z_p  = g_xz   + (size_t)b*LSEQ*(2*DI) + DI + d;
  float* y_p        = g_y    + (size_t)b*LSEQ*DI + d;

  for (int l = 0; l < LSEQ; l++){
    float dt = dt_p[(size_t)l*DI];                 // lane-broadcast
    float xc = xc_p[(size_t)l*DI];
    float Bn = bc_p[(size_t)l*XPN + n];
    float Cn = bc_p[(size_t)l*XPN + DSTATE + n];
    float dA = __expf(dt*a);
    h = fmaf(dA, h, dt*xc*Bn);
    float part = h*Cn;
    part += __shfl_xor_sync(~0u, part, 8, 16);
    part += __shfl_xor_sync(~0u, part, 4, 16);
    part += __shfl_xor_sync(~0u, part, 2, 16);
    part += __shfl_xor_sync(~0u, part, 1, 16);
    if (n == 0){
      float zz = z_p[(size_t)l*(2*DI)];
      float y = fmaf(Dd, xc, part);
      y = y * (zz / (1.f + __expf(-zz)));          // * SiLU(z)
      y_p[(size_t)l*DI] = y;
    }
  }
}

// ---------------- launch --------------------------------------------------
extern "C" void kernel_launch(void* const* d_in, const int* in_sizes, int n_in,
                              void* d_out, int out_size){
  const float* hidden    = (const float*)d_in[0];
  const float* norm_w    = (const float*)d_in[1];
  const float* in_proj_w = (const float*)d_in[2];
  const float* conv_w    = (const float*)d_in[3];
  const float* conv_b    = (const float*)d_in[4];
  const float* x_proj_w  = (const float*)d_in[5];
  const float* dt_proj_w = (const float*)d_in[6];
  const float* dt_proj_b = (const float*)d_in[7];
  const float* A_log     = (const float*)d_in[8];
  const float* Dp        = (const float*)d_in[9];
  const float* out_proj_w= (const float*)d_in[10];
  float* out = (float*)d_out;

  float *hnorm, *xz, *xc, *xdbl, *dt, *y;
  cudaGetSymbolAddress((void**)&hnorm, g_hnorm);
  cudaGetSymbolAddress((void**)&xz,    g_xz);
  cudaGetSymbolAddress((void**)&xc,    g_xc);
  cudaGetSymbolAddress((void**)&xdbl,  g_xdbl);
  cudaGetSymbolAddress((void**)&dt,    g_dt);
  cudaGetSymbolAddress((void**)&y,     g_y);

  // zero split-K accumulation targets
  cudaMemsetAsync(xdbl, 0, (size_t)NROWS*XPN*sizeof(float));
  cudaMemsetAsync(out,  0, (size_t)NROWS*DM*sizeof(float));

  // 1) rmsnorm
  rmsnorm_kernel<<<NROWS, 256>>>(hidden, norm_w);

  // 2) xz = hnorm @ in_proj_w.T   (2048 x 4096, K=1024)
  sgemm_tn<0><<<dim3(32,16,1), 256>>>(hnorm, DM, in_proj_w, DM,
                                      xz, 2*DI, 2*DI, DM, nullptr);

  // 3) causal conv + silu
  conv_silu_kernel<<<(NROWS*DI)/256, 256>>>(conv_w, conv_b);

  // 4) x_dbl = xc @ x_proj_w.T    (2048 x 96, K=2048) split-K=8
  sgemm_tn<2><<<dim3(1,16,8), 256>>>(xc, DI, x_proj_w, DI,
                                     xdbl, XPN, XPN, DI/8, nullptr);

  // 5) dt = softplus(x_dbl[:, :64] @ dt_proj_w.T + b)  (2048 x 2048, K=64)
  sgemm_tn<1><<<dim3(16,16,1), 256>>>(xdbl, XPN, dt_proj_w, DTRANK,
                                      dt, DI, DI, DTRANK, dt_proj_b);

  // 6) selective scan + gating epilogue -> y
  scan_kernel<<<(BATCH*DI*DSTATE)/256, 256>>>(A_log, Dp);

  // 7) out = y @ out_proj_w.T     (2048 x 1024, K=2048) split-K=2
  sgemm_tn<2><<<dim3(8,16,2), 256>>>(y, DI, out_proj_w, DI,
                                     out, DM, DM, DI/2, nullptr);

  // 8) residual passthrough (second tuple element)
  if (out_size >= 2*NROWS*DM){
    cudaMemcpyAsync(out + (size_t)NROWS*DM, hidden,
                    (size_t)NROWS*DM*sizeof(float),
                    cudaMemcpyDeviceToDevice);
  }
}

// round 3
// speedup vs baseline: 1.1886x; 1.1886x over previous
#include <cuda_runtime.h>
#include <cuda_bf16.h>
#include <math.h>
#include <stdint.h>

#define BATCH   2
#define LSEQ    1024
#define DM      1024
#define DI      2048
#define DSTATE  16
#define DTRANK  64
#define NROWS   (BATCH*LSEQ)   // 2048
#define XPN     96             // DT_RANK + 2*D_STATE

typedef __nv_bfloat16 bf16;

// ---------------- scratch (device globals; no allocation allowed) ----------
__device__ bf16  g_hn_hi[NROWS*DM],  g_hn_lo[NROWS*DM];
__device__ float g_xz[NROWS*2*DI];
__device__ float g_xc[NROWS*DI];
__device__ bf16  g_xc_hi[NROWS*DI],  g_xc_lo[NROWS*DI];
__device__ float g_xdbl[NROWS*XPN];
__device__ bf16  g_xd_hi[NROWS*XPN], g_xd_lo[NROWS*XPN];
__device__ float g_dt[NROWS*DI];
__device__ bf16  g_y_hi[NROWS*DI],   g_y_lo[NROWS*DI];
__device__ bf16  g_wi_hi[2*DI*DM],   g_wi_lo[2*DI*DM];
__device__ bf16  g_wx_hi[XPN*DI],    g_wx_lo[XPN*DI];
__device__ bf16  g_wd_hi[DI*DTRANK], g_wd_lo[DI*DTRANK];
__device__ bf16  g_wo_hi[DM*DI],     g_wo_lo[DM*DI];

// ---------------- small helpers -------------------------------------------
__device__ __forceinline__ float softplus_f(float x){
  return (x > 20.f) ? x : log1pf(expf(x));
}
__device__ __forceinline__ uint32_t s2u(const void* p){
  uint32_t a;
  asm("{ .reg .u64 t; cvta.to.shared.u64 t, %1; cvt.u32.u64 %0, t; }" : "=r"(a) : "l"(p));
  return a;
}
__device__ __forceinline__ void cp16(uint32_t s, const void* g){
  asm volatile("cp.async.cg.shared.global [%0], [%1], 16;" :: "r"(s), "l"(g));
}
#define CP_COMMIT() asm volatile("cp.async.commit_group;" ::: "memory")
#define CP_WAIT(n)  asm volatile("cp.async.wait_group %0;" :: "n"(n) : "memory")

__device__ __forceinline__ void ldsm4(uint32_t& r0, uint32_t& r1, uint32_t& r2,
                                      uint32_t& r3, uint32_t a){
  asm volatile("ldmatrix.sync.aligned.m8n8.x4.shared.b16 {%0,%1,%2,%3}, [%4];"
               : "=r"(r0), "=r"(r1), "=r"(r2), "=r"(r3) : "r"(a));
}
__device__ __forceinline__ void mma16816(float* c, const uint32_t* a,
                                         uint32_t b0, uint32_t b1){
  asm volatile(
    "mma.sync.aligned.m16n8k16.row.col.f32.bf16.bf16.f32 "
    "{%0,%1,%2,%3}, {%4,%5,%6,%7}, {%8,%9}, {%0,%1,%2,%3};"
    : "+f"(c[0]), "+f"(c[1]), "+f"(c[2]), "+f"(c[3])
    : "r"(a[0]), "r"(a[1]), "r"(a[2]), "r"(a[3]), "r"(b0), "r"(b1));
}

// ---------------- fp32 -> bf16 hi/lo split --------------------------------
__global__ void split_kernel(const float* __restrict__ s, bf16* __restrict__ hi,
                             bf16* __restrict__ lo, int n){
  int i = blockIdx.x*256 + threadIdx.x;
  if (i < n){
    float v = s[i];
    bf16 h = __float2bfloat16(v);
    hi[i] = h;
    lo[i] = __float2bfloat16(v - __bfloat162float(h));
  }
}

// ---------------- RMSNorm -> hi/lo ----------------------------------------
__global__ void rmsnorm_kernel(const float* __restrict__ x,
                               const float* __restrict__ w){
  int row = blockIdx.x;
  const float* xr = x + (size_t)row*DM;
  float ss = 0.f;
  for (int j = threadIdx.x; j < DM; j += 256){ float v = xr[j]; ss += v*v; }
  __shared__ float red[8];
  for (int o = 16; o; o >>= 1) ss += __shfl_xor_sync(~0u, ss, o);
  if ((threadIdx.x & 31) == 0) red[threadIdx.x >> 5] = ss;
  __syncthreads();
  if (threadIdx.x < 8){
    float v = red[threadIdx.x];
    for (int o = 4; o; o >>= 1) v += __shfl_xor_sync(0xff, v, o, 8);
    if (threadIdx.x == 0) red[0] = v;
  }
  __syncthreads();
  float rms = sqrtf(red[0]) * (1.0f/32.0f);
  float inv = 1.0f/(rms + 1e-5f);
  for (int j = threadIdx.x; j < DM; j += 256){
    float v = xr[j]*inv*w[j];
    bf16 h = __float2bfloat16(v);
    g_hn_hi[(size_t)row*DM + j] = h;
    g_hn_lo[(size_t)row*DM + j] = __float2bfloat16(v - __bfloat162float(h));
  }
}

// ---------------- HMMA (mma.sync) GEMM: C[m,n] = sum_k A[m,k]*B[n,k] ------
// bf16 hi/lo 3-term compensation: Ah*Bh + Ah*Bl + Al*Bh, fp32 accum.
// BM=128, BN=128, BK=64. 256 threads = 8 warps (2m x 4n), warp tile 64x32.
// EPI: 0 = store f32, 1 = softplus(acc+bias[n]) store, 2 = atomicAdd (split-K)
#define RSTRIDE 144            // 128B data + 16B pad per row
#define ARRB    (128*RSTRIDE)  // 18432 bytes per sub-array
#define STAGEB  (4*ARRB)       // Ah, Al, Bh, Bl
#define GSMEM   (2*STAGEB)     // double buffered: 147456

template<int EPI>
__global__ __launch_bounds__(256, 1) void gemm_mma(
    const bf16* __restrict__ Ahi, const bf16* __restrict__ Alo, int lda,
    const bf16* __restrict__ Bhi, const bf16* __restrict__ Blo, int ldb,
    float* __restrict__ C, int ldc, int N, int kc,
    const float* __restrict__ bias)
{
  extern __shared__ char smem_raw[];
  const uint32_t sbase = s2u(smem_raw);
  const int tid  = threadIdx.x;
  const int lane = tid & 31;
  const int w    = tid >> 5;
  const int wm   = w & 1;          // 0..1  (m half)
  const int wn   = w >> 1;         // 0..3  (n quarter)
  const int bm   = blockIdx.y * 128;
  const int bn   = blockIdx.x * 128;
  const int kbase = blockIdx.z * kc;
  const int nt   = kc / 64;

  float acc[4][4][4];
  #pragma unroll
  for (int i = 0; i < 4; i++)
    #pragma unroll
    for (int j = 0; j < 4; j++)
      #pragma unroll
      for (int r = 0; r < 4; r++) acc[i][j][r] = 0.f;

  auto load_stage = [&](int t){
    const int ko = kbase + t*64;
    const uint32_t sb = sbase + (uint32_t)(t & 1)*STAGEB;
    #pragma unroll
    for (int arr = 0; arr < 4; arr++){
      const bf16* src = (arr==0)?Ahi:(arr==1)?Alo:(arr==2)?Bhi:Blo;
      const int ld    = (arr < 2) ? lda : ldb;
      const int r0g   = (arr < 2) ? bm  : bn;
      const bool isB  = (arr >= 2);
      #pragma unroll
      for (int i = 0; i < 4; i++){
        int s = i*256 + tid;          // 0..1023
        int r = s >> 3, seg = s & 7;
        int gr = r0g + r;
        if (isB && gr > N-1) gr = N-1;
        cp16(sb + (uint32_t)arr*ARRB + (uint32_t)(r*RSTRIDE + seg*16),
             src + (size_t)gr*ld + ko + seg*8);
      }
    }
    CP_COMMIT();
  };

  load_stage(0);

  for (int t = 0; t < nt; t++){
    if (t + 1 < nt){ load_stage(t+1); CP_WAIT(1); }
    else           { CP_WAIT(0); }
    __syncthreads();

    const uint32_t sb = sbase + (uint32_t)(t & 1)*STAGEB;
    const uint32_t aH = sb + (uint32_t)((wm*64)*RSTRIDE);
    const uint32_t aL = aH + ARRB;
    const uint32_t bH = sb + 2u*ARRB + (uint32_t)((wn*32)*RSTRIDE);
    const uint32_t bL = bH + ARRB;
    const uint32_t lrow = (uint32_t)((lane & 15)*RSTRIDE);

    #pragma unroll
    for (int ks = 0; ks < 4; ks++){
      const uint32_t koff = (uint32_t)(ks*32 + (lane >> 4)*16);
      uint32_t bh[4][2], bl[4][2];
      {
        uint32_t q0,q1,q2,q3;
        ldsm4(q0,q1,q2,q3, bH + lrow + koff);
        bh[0][0]=q0; bh[0][1]=q2; bh[1][0]=q1; bh[1][1]=q3;
        ldsm4(q0,q1,q2,q3, bH + 16*RSTRIDE + lrow + koff);
        bh[2][0]=q0; bh[2][1]=q2; bh[3][0]=q1; bh[3][1]=q3;
        ldsm4(q0,q1,q2,q3, bL + lrow + koff);
        bl[0][0]=q0; bl[0][1]=q2; bl[1][0]=q1; bl[1][1]=q3;
        ldsm4(q0,q1,q2,q3, bL + 16*RSTRIDE + lrow + koff);
        bl[2][0]=q0; bl[2][1]=q2; bl[3][0]=q1; bl[3][1]=q3;
      }
      #pragma unroll
      for (int mi = 0; mi < 4; mi++){
        uint32_t ah[4], al[4];
        ldsm4(ah[0],ah[1],ah[2],ah[3], aH + (uint32_t)(mi*16*RSTRIDE) + lrow + koff);
        ldsm4(al[0],al[1],al[2],al[3], aL + (uint32_t)(mi*16*RSTRIDE) + lrow + koff);
        #pragma unroll
        for (int nj = 0; nj < 4; nj++){
          mma16816(acc[mi][nj], ah, bh[nj][0], bh[nj][1]);
          mma16816(acc[mi][nj], ah, bl[nj][0], bl[nj][1]);
          mma16816(acc[mi][nj], al, bh[nj][0], bh[nj][1]);
        }
      }
    }
    __syncthreads();
  }

  // epilogue: c0:(r, c), c1:(r, c+1), c2:(r+8, c), c3:(r+8, c+1)
  #pragma unroll
  for (int mi = 0; mi < 4; mi++){
    #pragma unroll
    for (int nj = 0; nj < 4; nj++){
      int m0 = bm + wm*64 + mi*16 + (lane >> 2);
      int n0 = bn + wn*32 + nj*8  + (lane & 3)*2;
      float* r0 = C + (size_t)m0*ldc;
      float* r1 = C + (size_t)(m0+8)*ldc;
      float v0 = acc[mi][nj][0], v1 = acc[mi][nj][1];
      float v2 = acc[mi][nj][2], v3 = acc[mi][nj][3];
      if (EPI == 1){
        v0 = softplus_f(v0 + bias[n0]);
        v2 = softplus_f(v2 + bias[n0]);
        if (n0+1 < N){ v1 = softplus_f(v1 + bias[n0+1]); v3 = softplus_f(v3 + bias[n0+1]); }
      }
      if (EPI == 2){
        if (n0   < N){ atomicAdd(&r0[n0],   v0); atomicAdd(&r1[n0],   v2); }
        if (n0+1 < N){ atomicAdd(&r0[n0+1], v1); atomicAdd(&r1[n0+1], v3); }
      } else {
        if (n0   < N){ r0[n0]   = v0; r1[n0]   = v2; }
        if (n0+1 < N){ r0[n0+1] = v1; r1[n0+1] = v3; }
      }
    }
  }
}

// ---------------- causal depthwise conv (k=4) + SiLU -> f32 + hi/lo -------
__global__ void conv_silu_kernel(const float* __restrict__ conv_w,
                                 const float* __restrict__ conv_b){
  int idx = blockIdx.x*256 + threadIdx.x;          // over NROWS*DI
  int d   = idx & (DI-1);
  int row = idx >> 11;
  int l   = row & (LSEQ-1);
  int b   = row >> 10;
  float s = conv_b[d];
  const float* xcol = g_xz + ((size_t)b*LSEQ)*(2*DI) + d;
  #pragma unroll
  for (int k = 0; k < 4; k++){
    int ls = l - 3 + k;
    if (ls >= 0) s = fmaf(xcol[(size_t)ls*(2*DI)], conv_w[d*4+k], s);
  }
  s = s / (1.f + __expf(-s));
  g_xc[idx] = s;
  bf16 h = __float2bfloat16(s);
  g_xc_hi[idx] = h;
  g_xc_lo[idx] = __float2bfloat16(s - __bfloat162float(h));
}

// ---------------- selective scan ------------------------------------------
__global__ void scan_kernel(const float* __restrict__ A_log,
                            const float* __restrict__ Dp){
  int gt = blockIdx.x*blockDim.x + threadIdx.x;    // 65536 threads
  int n  = gt & 15;
  int g  = gt >> 4;
  int d  = g & (DI-1);
  int b  = g >> 11;
  float a  = -expf(A_log[d*DSTATE + n]);
  float Dd = Dp[d];
  float h  = 0.f;
  const float* dt_p = g_dt   + (size_t)b*LSEQ*DI + d;
  const float* xc_p = g_xc   + (size_t)b*LSEQ*DI + d;
  const float* bc_p = g_xdbl + (size_t)b*LSEQ*XPN + DTRANK;
  const float* z_p  = g_xz   + (size_t)b*LSEQ*(2*DI) + DI + d;
  bf16* yh_p        = g_y_hi + (size_t)b*LSEQ*DI + d;
  bf16* yl_p        = g_y_lo + (size_t)b*LSEQ*DI + d;

  for (int l = 0; l < LSEQ; l++){
    float dt = dt_p[(size_t)l*DI];
    float xc = xc_p[(size_t)l*DI];
    float Bn = bc_p[(size_t)l*XPN + n];
    float Cn = bc_p[(size_t)l*XPN + DSTATE + n];
    float dA = __expf(dt*a);
    h = fmaf(dA, h, dt*xc*Bn);
    float part = h*Cn;
    part += __shfl_xor_sync(~0u, part, 8, 16);
    part += __shfl_xor_sync(~0u, part, 4, 16);
    part += __shfl_xor_sync(~0u, part, 2, 16);
    part += __shfl_xor_sync(~0u, part, 1, 16);
    if (n == 0){
      float zz = z_p[(size_t)l*(2*DI)];
      float y = fmaf(Dd, xc, part);
      y = y * (zz / (1.f + __expf(-zz)));
      bf16 hh = __float2bfloat16(y);
      yh_p[(size_t)l*DI] = hh;
      yl_p[(size_t)l*DI] = __float2bfloat16(y - __bfloat162float(hh));
    }
  }
}

// ---------------- launch --------------------------------------------------
extern "C" void kernel_launch(void* const* d_in, const int* in_sizes, int n_in,
                              void* d_out, int out_size){
  const float* hidden    = (const float*)d_in[0];
  const float* norm_w    = (const float*)d_in[1];
  const float* in_proj_w = (const float*)d_in[2];
  const float* conv_w    = (const float*)d_in[3];
  const float* conv_b    = (const float*)d_in[4];
  const float* x_proj_w  = (const float*)d_in[5];
  const float* dt_proj_w = (const float*)d_in[6];
  const float* dt_proj_b = (const float*)d_in[7];
  const float* A_log     = (const float*)d_in[8];
  const float* Dp        = (const float*)d_in[9];
  const float* out_proj_w= (const float*)d_in[10];
  float* out = (float*)d_out;

  cudaFuncSetAttribute(gemm_mma<0>, cudaFuncAttributeMaxDynamicSharedMemorySize, GSMEM);
  cudaFuncSetAttribute(gemm_mma<1>, cudaFuncAttributeMaxDynamicSharedMemorySize, GSMEM);
  cudaFuncSetAttribute(gemm_mma<2>, cudaFuncAttributeMaxDynamicSharedMemorySize, GSMEM);

  bf16 *hn_hi,*hn_lo,*xc_hi,*xc_lo,*xd_hi,*xd_lo,*y_hi,*y_lo;
  bf16 *wi_hi,*wi_lo,*wx_hi,*wx_lo,*wd_hi,*wd_lo,*wo_hi,*wo_lo;
  float *xz,*xc,*xdbl,*dt;
  cudaGetSymbolAddress((void**)&hn_hi, g_hn_hi);  cudaGetSymbolAddress((void**)&hn_lo, g_hn_lo);
  cudaGetSymbolAddress((void**)&xc_hi, g_xc_hi);  cudaGetSymbolAddress((void**)&xc_lo, g_xc_lo);
  cudaGetSymbolAddress((void**)&xd_hi, g_xd_hi);  cudaGetSymbolAddress((void**)&xd_lo, g_xd_lo);
  cudaGetSymbolAddress((void**)&y_hi,  g_y_hi);   cudaGetSymbolAddress((void**)&y_lo,  g_y_lo);
  cudaGetSymbolAddress((void**)&wi_hi, g_wi_hi);  cudaGetSymbolAddress((void**)&wi_lo, g_wi_lo);
  cudaGetSymbolAddress((void**)&wx_hi, g_wx_hi);  cudaGetSymbolAddress((void**)&wx_lo, g_wx_lo);
  cudaGetSymbolAddress((void**)&wd_hi, g_wd_hi);  cudaGetSymbolAddress((void**)&wd_lo, g_wd_lo);
  cudaGetSymbolAddress((void**)&wo_hi, g_wo_hi);  cudaGetSymbolAddress((void**)&wo_lo, g_wo_lo);
  cudaGetSymbolAddress((void**)&xz,   g_xz);
  cudaGetSymbolAddress((void**)&xc,   g_xc);
  cudaGetSymbolAddress((void**)&xdbl, g_xdbl);
  cudaGetSymbolAddress((void**)&dt,   g_dt);

  // weight hi/lo splits (memory-bound, ~26MB total traffic)
  split_kernel<<<(2*DI*DM+255)/256, 256>>>(in_proj_w,  wi_hi, wi_lo, 2*DI*DM);
  split_kernel<<<(XPN*DI+255)/256, 256>>>(x_proj_w,    wx_hi, wx_lo, XPN*DI);
  split_kernel<<<(DI*DTRANK+255)/256, 256>>>(dt_proj_w, wd_hi, wd_lo, DI*DTRANK);
  split_kernel<<<(DM*DI+255)/256, 256>>>(out_proj_w,   wo_hi, wo_lo, DM*DI);

  // zero split-K accumulation target
  cudaMemsetAsync(xdbl, 0, (size_t)NROWS*XPN*sizeof(float));

  // 1) rmsnorm -> hn hi/lo
  rmsnorm_kernel<<<NROWS, 256>>>(hidden, norm_w);

  // 2) xz = hnorm @ in_proj_w.T   (2048 x 4096, K=1024)
  gemm_mma<0><<<dim3(32,16,1), 256, GSMEM>>>(hn_hi, hn_lo, DM, wi_hi, wi_lo, DM,
                                             xz, 2*DI, 2*DI, DM, nullptr);

  // 3) causal conv + silu -> xc f32 + hi/lo
  conv_silu_kernel<<<(NROWS*DI)/256, 256>>>(conv_w, conv_b);

  // 4) x_dbl = xc @ x_proj_w.T    (2048 x 96, K=2048) split-K=8, atomicAdd
  gemm_mma<2><<<dim3(1,16,8), 256, GSMEM>>>(xc_hi, xc_lo, DI, wx_hi, wx_lo, DI,
                                            xdbl, XPN, XPN, DI/8, nullptr);

  // 4b) split xdbl -> hi/lo for dt GEMM
  split_kernel<<<(NROWS*XPN+255)/256, 256>>>(xdbl, xd_hi, xd_lo, NROWS*XPN);

  // 5) dt = softplus(x_dbl[:,:64] @ dt_proj_w.T + b)  (2048 x 2048, K=64)
  gemm_mma<1><<<dim3(16,16,1), 256, GSMEM>>>(xd_hi, xd_lo, XPN, wd_hi, wd_lo, DTRANK,
                                             dt, DI, DI, DTRANK, dt_proj_b);

  // 6) selective scan + gating -> y hi/lo
  scan_kernel<<<(BATCH*DI*DSTATE)/256, 256>>>(A_log, Dp);

  // 7) out = y @ out_proj_w.T     (2048 x 1024, K=2048)
  gemm_mma<0><<<dim3(8,16,1), 256, GSMEM>>>(y_hi, y_lo, DI, wo_hi, wo_lo, DI,
                                            out, DM, DM, DI, nullptr);

  // 8) residual passthrough
  if (out_size >= 2*NROWS*DM){
    cudaMemcpyAsync(out + (size_t)NROWS*DM, hidden,
                    (size_t)NROWS*DM*sizeof(float),
                    cudaMemcpyDeviceToDevice);
  }
}